// round 2
// baseline (speedup 1.0000x reference)
#include <cuda_runtime.h>
#include <math.h>

#define B_ 32
#define C_ 64
#define H_ 64
#define W_ 64
#define E_ 8
#define HW_ (H_*W_)
#define TW 128   // hw tile per block in main kernel

// scratch (no device allocation allowed)
__device__ float g_S[B_*C_*9];   // window sums  [b][c][dy*3+dx]
__device__ float g_val[B_];      // top1 prob per batch
__device__ int   g_idx[B_];      // top1 expert per batch

// ---------------------------------------------------------------------------
// Kernel 1: per-(b,c) 9 window sums. Window (dy,dx) = sum over rows [dy,dy+61],
// cols [dx,dx+61]. Element (y,x) belongs to dy in [max(0,y-61),min(2,y)], same for dx.
// ---------------------------------------------------------------------------
__global__ void k_winsum(const float* __restrict__ x) {
    int bc = blockIdx.x;                       // 0 .. B*C-1
    const float* img = x + (size_t)bc * HW_;
    float acc[9];
#pragma unroll
    for (int k = 0; k < 9; k++) acc[k] = 0.f;

    for (int i = threadIdx.x; i < HW_; i += 256) {
        int y  = i >> 6;
        int xx = i & 63;
        float v = img[i];
        int dy0 = y - 61;  if (dy0 < 0) dy0 = 0;
        int dy1 = y;       if (dy1 > 2) dy1 = 2;
        int dx0 = xx - 61; if (dx0 < 0) dx0 = 0;
        int dx1 = xx;      if (dx1 > 2) dx1 = 2;
        for (int dy = dy0; dy <= dy1; dy++)
            for (int dx = dx0; dx <= dx1; dx++)
                acc[dy*3+dx] += v;
    }
    // warp reduce
#pragma unroll
    for (int off = 16; off; off >>= 1)
#pragma unroll
        for (int k = 0; k < 9; k++)
            acc[k] += __shfl_down_sync(0xffffffffu, acc[k], off);

    __shared__ float sred[8][9];
    int warp = threadIdx.x >> 5, lane = threadIdx.x & 31;
    if (lane == 0)
#pragma unroll
        for (int k = 0; k < 9; k++) sred[warp][k] = acc[k];
    __syncthreads();
    if (threadIdx.x < 9) {
        float s = 0.f;
#pragma unroll
        for (int w = 0; w < 8; w++) s += sred[w][threadIdx.x];
        g_S[bc*9 + threadIdx.x] = s;
    }
}

// ---------------------------------------------------------------------------
// Kernel 2: gating codes, softmax over E=8, top-1; writes expert_weights and
// per-batch (idx, val). One block, 256 threads = 32 b x 8 e (8-lane groups).
// ---------------------------------------------------------------------------
__global__ void k_gate(const float* __restrict__ gate_w,
                       const float* __restrict__ gate_b,
                       float* __restrict__ ew /* may be null */) {
    int t = threadIdx.x;
    int b = t >> 3;
    int e = t & 7;

    const float* Wg = gate_w + e * (C_*9);   // 576 contiguous
    const float* Sb = g_S    + b * (C_*9);
    float g = 0.f;
#pragma unroll 8
    for (int i = 0; i < C_*9; i++) g += Wg[i] * Sb[i];
    g += 3844.0f * gate_b[e];   // 62*62 positions of bias, summed

    int lane = t & 31;
    // max over 8-lane group
    float m = g;
#pragma unroll
    for (int s = 4; s; s >>= 1) m = fmaxf(m, __shfl_xor_sync(0xffffffffu, m, s));
    float pe = expf(g - m);
    float ssum = pe;
#pragma unroll
    for (int s = 4; s; s >>= 1) ssum += __shfl_xor_sync(0xffffffffu, ssum, s);
    float top = 1.0f / ssum;    // max prob: exp(0)/sum

    unsigned bal = __ballot_sync(0xffffffffu, g == m);
    int base = (lane >> 3) * 8;
    int idx = __ffs((bal >> base) & 0xFFu) - 1;  // first (lowest-e) maximum

    if (ew) ew[b*E_ + e] = (e == idx) ? top : 0.f;
    if (e == 0) { g_idx[b] = idx; g_val[b] = top; }
}

// ---------------------------------------------------------------------------
// Kernel 3: out[b,f,hw] = val[b] * sum_c W[idx[b]][f][c] * x[b,c,hw]
// Block: (hw tile of 128) x (batch). 256 threads, each computes 4 f x 8 hw.
// Shared: W transposed+prescaled [c][f] 16KB + x tile [c][hw] 32KB = 48KB.
// ---------------------------------------------------------------------------
__global__ void __launch_bounds__(256) k_main(const float* __restrict__ x,
                                              const float* __restrict__ expert_w,
                                              float* __restrict__ out) {
    __shared__ float WsT[C_][C_];      // [c][f]
    __shared__ float xs[C_][TW];       // [c][j]

    int b  = blockIdx.y;
    int t0 = blockIdx.x * TW;

    int idx = g_idx[b];
    float scale = g_val[b];
    const float* Wsrc = expert_w + (size_t)idx * C_ * C_;   // [f][c]

    // load W transposed and pre-scaled
    for (int i = threadIdx.x; i < C_*C_; i += 256) {
        int f = i >> 6, c = i & 63;
        WsT[c][f] = scale * Wsrc[i];
    }
    // load x tile (vectorized)
    const float* xb = x + (size_t)b * C_ * HW_ + t0;
    for (int i = threadIdx.x * 4; i < C_*TW; i += 256*4) {
        int c = i / TW, j = i % TW;
        float4 v = *(const float4*)(xb + (size_t)c * HW_ + j);
        *(float4*)&xs[c][j] = v;
    }
    __syncthreads();

    int f0 = (threadIdx.x >> 4) * 4;     // 16 f-groups of 4
    int j0 = (threadIdx.x & 15) * 8;     // 16 hw-groups of 8

    float acc[4][8];
#pragma unroll
    for (int i = 0; i < 4; i++)
#pragma unroll
        for (int j = 0; j < 8; j++) acc[i][j] = 0.f;

#pragma unroll 8
    for (int c = 0; c < C_; c++) {
        float4 w  = *(const float4*)&WsT[c][f0];
        float4 xa = *(const float4*)&xs[c][j0];
        float4 xc = *(const float4*)&xs[c][j0+4];
        float wv[4] = {w.x, w.y, w.z, w.w};
        float xv[8] = {xa.x, xa.y, xa.z, xa.w, xc.x, xc.y, xc.z, xc.w};
#pragma unroll
        for (int i = 0; i < 4; i++)
#pragma unroll
            for (int j = 0; j < 8; j++)
                acc[i][j] = fmaf(wv[i], xv[j], acc[i][j]);
    }

    float* ob = out + (size_t)b * C_ * HW_ + t0;
#pragma unroll
    for (int i = 0; i < 4; i++) {
        float4 r0 = make_float4(acc[i][0], acc[i][1], acc[i][2], acc[i][3]);
        float4 r1 = make_float4(acc[i][4], acc[i][5], acc[i][6], acc[i][7]);
        *(float4*)(ob + (size_t)(f0+i) * HW_ + j0)     = r0;
        *(float4*)(ob + (size_t)(f0+i) * HW_ + j0 + 4) = r1;
    }
}

// ---------------------------------------------------------------------------
extern "C" void kernel_launch(void* const* d_in, const int* in_sizes, int n_in,
                              void* d_out, int out_size) {
    const float* x        = (const float*)d_in[0];   // [32,64,64,64]
    const float* gate_w   = (const float*)d_in[1];   // [8,64,3,3]
    const float* gate_b   = (const float*)d_in[2];   // [8]
    const float* expert_w = (const float*)d_in[3];   // [8,64,64]
    float* out = (float*)d_out;

    const int OUT_MAIN = B_*C_*HW_;                  // 2097152
    float* ew = (out_size >= OUT_MAIN + B_*E_) ? (out + OUT_MAIN) : nullptr;

    k_winsum<<<B_*C_, 256>>>(x);
    k_gate<<<1, 256>>>(gate_w, gate_b, ew);
    k_main<<<dim3(HW_/TW, B_), 256>>>(x, expert_w, out);
}

// round 3
// speedup vs baseline: 1.5525x; 1.5525x over previous
#include <cuda_runtime.h>
#include <math.h>

#define B_ 32
#define C_ 64
#define H_ 64
#define W_ 64
#define E_ 8
#define HW_ (H_*W_)
#define TW 128   // hw tile per block in main kernel

// scratch (no device allocation allowed)
__device__ __align__(16) float g_S[B_*C_*9];   // window sums  [b][c][dy*3+dx]
__device__ float g_val[B_];      // top1 prob per batch
__device__ int   g_idx[B_];      // top1 expert per batch

// ---------------------------------------------------------------------------
// Kernel 1: per-(b,c) 9 window sums via inclusion-exclusion.
// Window (dy,dx) covers rows [dy,dy+61] x cols [dx,dx+61].
// S[dy][dx] = Total - R(excluded rows) - C(excluded cols) + corner terms.
// Excluded rows: dy=0 -> {62,63}; dy=1 -> {0,63}; dy=2 -> {0,1}. Same for cols.
// Block = 128 threads, one (b,c) image, float4 loads.
// ---------------------------------------------------------------------------
__global__ void __launch_bounds__(128) k_winsum(const float* __restrict__ x) {
    int bc = blockIdx.x;
    const float4* img4 = (const float4*)(x + (size_t)bc * HW_);

    int tid = threadIdx.x;
    int xq  = tid & 15;      // float4 column (0..15), constant per thread
    int ty  = tid >> 4;      // starting row group

    float T = 0.f;
    float R0=0.f, R1=0.f, R2=0.f, R3=0.f;   // rows 0,1,62,63
    float C0=0.f, C1=0.f, C2=0.f, C3=0.f;   // cols 0,1,62,63

#pragma unroll
    for (int k = 0; k < 8; k++) {
        float4 v = img4[tid + k*128];
        float s = (v.x + v.y) + (v.z + v.w);
        T += s;
        int y = ty + k*8;
        if (y == 0)       R0 += s;
        else if (y == 1)  R1 += s;
        else if (y == 62) R2 += s;
        else if (y == 63) R3 += s;
        if (xq == 0)       { C0 += v.x; C1 += v.y; }
        else if (xq == 15) { C2 += v.z; C3 += v.w; }
    }

    // reduce 9 values across the block
    float a[9] = {T, R0, R1, R2, R3, C0, C1, C2, C3};
#pragma unroll
    for (int off = 16; off; off >>= 1)
#pragma unroll
        for (int k = 0; k < 9; k++)
            a[k] += __shfl_down_sync(0xffffffffu, a[k], off);

    __shared__ float sred[4][9];
    int warp = tid >> 5, lane = tid & 31;
    if (lane == 0)
#pragma unroll
        for (int k = 0; k < 9; k++) sred[warp][k] = a[k];
    __syncthreads();

    if (tid == 0) {
        float r[9];
#pragma unroll
        for (int k = 0; k < 9; k++)
            r[k] = ((sred[0][k] + sred[1][k]) + (sred[2][k] + sred[3][k]));
        // corner values at (y,x) in {0,1,62,63}^2
        const float* img = x + (size_t)bc * HW_;
        const int yv[4] = {0, 1, 62, 63};
        float cv[4][4];
#pragma unroll
        for (int i = 0; i < 4; i++)
#pragma unroll
            for (int j = 0; j < 4; j++)
                cv[i][j] = img[yv[i]*64 + yv[j]];
        // excluded-edge index pairs per d (indices into {0,1,62,63} order)
        const int e0[3] = {2, 0, 0};
        const int e1[3] = {3, 3, 1};
        float* Sout = g_S + bc*9;
#pragma unroll
        for (int dy = 0; dy < 3; dy++) {
            int ya = e0[dy], yb = e1[dy];
#pragma unroll
            for (int dx = 0; dx < 3; dx++) {
                int xa = e0[dx], xb = e1[dx];
                float s = r[0]
                        - (r[1+ya] + r[1+yb])
                        - (r[5+xa] + r[5+xb])
                        + ((cv[ya][xa] + cv[ya][xb]) + (cv[yb][xa] + cv[yb][xb]));
                Sout[dy*3+dx] = s;
            }
        }
    }
}

// ---------------------------------------------------------------------------
// Kernel 2: gating codes, softmax over E=8, top-1. One block, 256 threads =
// 32 b x 8 e. float4 dot of 576 elements.
// ---------------------------------------------------------------------------
__global__ void k_gate(const float* __restrict__ gate_w,
                       const float* __restrict__ gate_b,
                       float* __restrict__ ew /* may be null */) {
    int t = threadIdx.x;
    int b = t >> 3;
    int e = t & 7;

    const float4* Wg = (const float4*)(gate_w + e * (C_*9));
    const float4* Sb = (const float4*)(g_S    + b * (C_*9));
    float g = 0.f;
#pragma unroll 4
    for (int i = 0; i < (C_*9)/4; i++) {
        float4 w = Wg[i], s = Sb[i];
        g += w.x*s.x + w.y*s.y + w.z*s.z + w.w*s.w;
    }
    g += 3844.0f * gate_b[e];   // 62*62 positions of bias, summed

    int lane = t & 31;
    float m = g;
#pragma unroll
    for (int s = 4; s; s >>= 1) m = fmaxf(m, __shfl_xor_sync(0xffffffffu, m, s));
    float pe = expf(g - m);
    float ssum = pe;
#pragma unroll
    for (int s = 4; s; s >>= 1) ssum += __shfl_xor_sync(0xffffffffu, ssum, s);
    float top = 1.0f / ssum;

    unsigned bal = __ballot_sync(0xffffffffu, g == m);
    int base = (lane >> 3) * 8;
    int idx = __ffs((bal >> base) & 0xFFu) - 1;

    if (ew) ew[b*E_ + e] = (e == idx) ? top : 0.f;
    if (e == 0) { g_idx[b] = idx; g_val[b] = top; }
}

// ---------------------------------------------------------------------------
// Kernel 3: out[b,f,hw] = val[b] * sum_c W[idx[b]][f][c] * x[b,c,hw]
// Packed-fp32 (fma.rn.f32x2) register-blocked GEMM: each thread computes
// 4 f x 8 hw as 4x4 f32x2 accumulators (pair axis = contiguous hw).
// Shared: W^T prescaled [c][f] 16KB + x tile [c][128] 32KB = 48KB.
// ---------------------------------------------------------------------------
__device__ __forceinline__ void fma2(unsigned long long& d,
                                     unsigned long long a,
                                     unsigned long long b) {
    asm("fma.rn.f32x2 %0, %1, %2, %0;" : "+l"(d) : "l"(a), "l"(b));
}

__global__ void __launch_bounds__(256) k_main(const float* __restrict__ x,
                                              const float* __restrict__ expert_w,
                                              float* __restrict__ out) {
    __shared__ float WsT[C_][C_];      // [c][f], prescaled
    __shared__ float xs[C_][TW];       // [c][j]

    int b  = blockIdx.y;
    int t0 = blockIdx.x * TW;

    int idx = g_idx[b];
    float scale = g_val[b];
    const float* Wsrc = expert_w + (size_t)idx * C_ * C_;   // [f][c]

    for (int i = threadIdx.x; i < C_*C_; i += 256) {
        int f = i >> 6, c = i & 63;
        WsT[c][f] = scale * Wsrc[i];
    }
    const float* xb = x + (size_t)b * C_ * HW_ + t0;
    for (int i = threadIdx.x * 4; i < C_*TW; i += 256*4) {
        int c = i / TW, j = i % TW;
        *(float4*)&xs[c][j] = *(const float4*)(xb + (size_t)c * HW_ + j);
    }
    __syncthreads();

    int f0 = (threadIdx.x >> 4) * 4;     // 16 f-groups of 4 (lanes 0-15 share)
    int j0 = (threadIdx.x & 15) * 8;     // 16 hw-groups of 8

    unsigned long long acc[4][4];
#pragma unroll
    for (int i = 0; i < 4; i++)
#pragma unroll
        for (int j = 0; j < 4; j++) acc[i][j] = 0ull;   // (0.0f, 0.0f)

#pragma unroll 4
    for (int c = 0; c < C_; c++) {
        float4 w = *(const float4*)&WsT[c][f0];
        unsigned long long wd[4];
        asm("mov.b64 %0, {%1, %1};" : "=l"(wd[0]) : "f"(w.x));
        asm("mov.b64 %0, {%1, %1};" : "=l"(wd[1]) : "f"(w.y));
        asm("mov.b64 %0, {%1, %1};" : "=l"(wd[2]) : "f"(w.z));
        asm("mov.b64 %0, {%1, %1};" : "=l"(wd[3]) : "f"(w.w));
        ulonglong2 xa = *(const ulonglong2*)&xs[c][j0];      // pairs j0..j0+3
        ulonglong2 xc = *(const ulonglong2*)&xs[c][j0+4];    // pairs j0+4..j0+7
        unsigned long long xv[4] = {xa.x, xa.y, xc.x, xc.y};
#pragma unroll
        for (int i = 0; i < 4; i++)
#pragma unroll
            for (int j = 0; j < 4; j++)
                fma2(acc[i][j], wd[i], xv[j]);
    }

    float* ob = out + (size_t)b * C_ * HW_ + t0;
#pragma unroll
    for (int i = 0; i < 4; i++) {
        ulonglong2 r0; r0.x = acc[i][0]; r0.y = acc[i][1];
        ulonglong2 r1; r1.x = acc[i][2]; r1.y = acc[i][3];
        *(ulonglong2*)(ob + (size_t)(f0+i) * HW_ + j0)     = r0;
        *(ulonglong2*)(ob + (size_t)(f0+i) * HW_ + j0 + 4) = r1;
    }
}

// ---------------------------------------------------------------------------
extern "C" void kernel_launch(void* const* d_in, const int* in_sizes, int n_in,
                              void* d_out, int out_size) {
    const float* x        = (const float*)d_in[0];   // [32,64,64,64]
    const float* gate_w   = (const float*)d_in[1];   // [8,64,3,3]
    const float* gate_b   = (const float*)d_in[2];   // [8]
    const float* expert_w = (const float*)d_in[3];   // [8,64,64]
    float* out = (float*)d_out;

    const int OUT_MAIN = B_*C_*HW_;                  // 2097152
    float* ew = (out_size >= OUT_MAIN + B_*E_) ? (out + OUT_MAIN) : nullptr;

    k_winsum<<<B_*C_, 128>>>(x);
    k_gate<<<1, 256>>>(gate_w, gate_b, ew);
    k_main<<<dim3(HW_/TW, B_), 256>>>(x, expert_w, out);
}

// round 5
// speedup vs baseline: 2.6120x; 1.6825x over previous
#include <cuda_runtime.h>
#include <cuda_bf16.h>
#include <math.h>
#include <stdint.h>

#define B_ 32
#define C_ 64
#define H_ 64
#define W_ 64
#define E_ 8
#define HW_ (H_*W_)

// ---------------- scratch -------------------------------------------------
__device__ __align__(16) float g_S[B_*C_*9];
__device__ float g_val[B_];
__device__ int   g_idx[B_];

// ---------------------------------------------------------------------------
// Kernel 1: per-(b,c) 9 window sums via inclusion-exclusion (R3, passing).
// ---------------------------------------------------------------------------
__global__ void __launch_bounds__(128) k_winsum(const float* __restrict__ x) {
    int bc = blockIdx.x;
    const float4* img4 = (const float4*)(x + (size_t)bc * HW_);

    int tid = threadIdx.x;
    int xq  = tid & 15;
    int ty  = tid >> 4;

    float T = 0.f;
    float R0=0.f, R1=0.f, R2=0.f, R3=0.f;
    float C0=0.f, C1=0.f, C2=0.f, C3=0.f;

#pragma unroll
    for (int k = 0; k < 8; k++) {
        float4 v = img4[tid + k*128];
        float s = (v.x + v.y) + (v.z + v.w);
        T += s;
        int y = ty + k*8;
        if (y == 0)       R0 += s;
        else if (y == 1)  R1 += s;
        else if (y == 62) R2 += s;
        else if (y == 63) R3 += s;
        if (xq == 0)       { C0 += v.x; C1 += v.y; }
        else if (xq == 15) { C2 += v.z; C3 += v.w; }
    }

    float a[9] = {T, R0, R1, R2, R3, C0, C1, C2, C3};
#pragma unroll
    for (int off = 16; off; off >>= 1)
#pragma unroll
        for (int k = 0; k < 9; k++)
            a[k] += __shfl_down_sync(0xffffffffu, a[k], off);

    __shared__ float sred[4][9];
    int warp = tid >> 5, lane = tid & 31;
    if (lane == 0)
#pragma unroll
        for (int k = 0; k < 9; k++) sred[warp][k] = a[k];
    __syncthreads();

    if (tid == 0) {
        float r[9];
#pragma unroll
        for (int k = 0; k < 9; k++)
            r[k] = ((sred[0][k] + sred[1][k]) + (sred[2][k] + sred[3][k]));
        const float* img = x + (size_t)bc * HW_;
        const int yv[4] = {0, 1, 62, 63};
        float cv[4][4];
#pragma unroll
        for (int i = 0; i < 4; i++)
#pragma unroll
            for (int j = 0; j < 4; j++)
                cv[i][j] = img[yv[i]*64 + yv[j]];
        const int e0[3] = {2, 0, 0};
        const int e1[3] = {3, 3, 1};
        float* Sout = g_S + bc*9;
#pragma unroll
        for (int dy = 0; dy < 3; dy++) {
            int ya = e0[dy], yb = e1[dy];
#pragma unroll
            for (int dx = 0; dx < 3; dx++) {
                int xa = e0[dx], xb = e1[dx];
                Sout[dy*3+dx] = r[0]
                    - (r[1+ya] + r[1+yb]) - (r[5+xa] + r[5+xb])
                    + ((cv[ya][xa] + cv[ya][xb]) + (cv[yb][xa] + cv[yb][xb]));
            }
        }
    }
}

// ---------------------------------------------------------------------------
// Kernel 2: gating + softmax + top-1 (unchanged, passing)
// ---------------------------------------------------------------------------
__global__ void k_gate(const float* __restrict__ gate_w,
                       const float* __restrict__ gate_b,
                       float* __restrict__ ew) {
    int t = threadIdx.x;
    int b = t >> 3;
    int e = t & 7;

    const float4* Wg = (const float4*)(gate_w + e * (C_*9));
    const float4* Sb = (const float4*)(g_S    + b * (C_*9));
    float g = 0.f;
#pragma unroll 4
    for (int i = 0; i < (C_*9)/4; i++) {
        float4 w = Wg[i], s = Sb[i];
        g += w.x*s.x + w.y*s.y + w.z*s.z + w.w*s.w;
    }
    g += 3844.0f * gate_b[e];

    int lane = t & 31;
    float m = g;
#pragma unroll
    for (int s = 4; s; s >>= 1) m = fmaxf(m, __shfl_xor_sync(0xffffffffu, m, s));
    float pe = expf(g - m);
    float ssum = pe;
#pragma unroll
    for (int s = 4; s; s >>= 1) ssum += __shfl_xor_sync(0xffffffffu, ssum, s);
    float top = 1.0f / ssum;

    unsigned bal = __ballot_sync(0xffffffffu, g == m);
    int base = (lane >> 3) * 8;
    int idx = __ffs((bal >> base) & 0xFFu) - 1;

    if (ew) ew[b*E_ + e] = (e == idx) ? top : 0.f;
    if (e == 0) { g_idx[b] = idx; g_val[b] = top; }
}

// ---------------------------------------------------------------------------
// Kernel 3: HMMA bf16 GEMM via mma.sync (no tcgen05 on plain compute_103).
// out[b,f,hw] = val[b] * sum_c W[idx[b]][f][c] * x[b,c,hw]
// 3-term bf16 split: Wh*xh + Wh*xl + Wl*xh accumulated in fp32.
// CTA: 64 f x 128 hw tile; 8 warps, warp = 32f x 32hw.
// A = W (prescaled) bf16 hi/lo in smem [f][c] (pad 144B rows), ldmatrix.x4.
// B = x bf16 hi/lo in smem [c][hw] (pad 272B rows), ldmatrix.x4.trans.
// ---------------------------------------------------------------------------
#define WS_STRIDE 144   // bytes per A row (64 bf16 + pad)
#define XS_STRIDE 272   // bytes per B row (128 bf16 + pad)
#define WS_BYTES  (64*WS_STRIDE)           // 9216
#define XS_BYTES  (64*XS_STRIDE)           // 17408
#define SMEM_TOT  (2*WS_BYTES + 2*XS_BYTES)  // 53248

__device__ __forceinline__ uint32_t smem_u32(const void* p) {
    uint32_t a;
    asm("{ .reg .u64 t; cvta.to.shared.u64 t, %1; cvt.u32.u64 %0, t; }" : "=r"(a) : "l"(p));
    return a;
}

__device__ __forceinline__ void ldmat4(uint32_t* r, uint32_t addr) {
    asm volatile("ldmatrix.sync.aligned.m8n8.x4.shared.b16 {%0,%1,%2,%3}, [%4];"
        : "=r"(r[0]), "=r"(r[1]), "=r"(r[2]), "=r"(r[3]) : "r"(addr));
}
__device__ __forceinline__ void ldmat4t(uint32_t* r, uint32_t addr) {
    asm volatile("ldmatrix.sync.aligned.m8n8.x4.trans.shared.b16 {%0,%1,%2,%3}, [%4];"
        : "=r"(r[0]), "=r"(r[1]), "=r"(r[2]), "=r"(r[3]) : "r"(addr));
}
__device__ __forceinline__ void mma16816(float* d, const uint32_t* a, uint32_t b0, uint32_t b1) {
    asm volatile("mma.sync.aligned.m16n8k16.row.col.f32.bf16.bf16.f32 "
        "{%0,%1,%2,%3}, {%4,%5,%6,%7}, {%8,%9}, {%0,%1,%2,%3};"
        : "+f"(d[0]), "+f"(d[1]), "+f"(d[2]), "+f"(d[3])
        : "r"(a[0]), "r"(a[1]), "r"(a[2]), "r"(a[3]), "r"(b0), "r"(b1));
}

__device__ __forceinline__ uint32_t pack_hi(float a, float b) {
    __nv_bfloat162 p = __halves2bfloat162(__float2bfloat16(a), __float2bfloat16(b));
    return *(uint32_t*)&p;
}
__device__ __forceinline__ uint32_t pack_lo(float a, float b) {
    float ra = a - __bfloat162float(__float2bfloat16(a));
    float rb = b - __bfloat162float(__float2bfloat16(b));
    __nv_bfloat162 p = __halves2bfloat162(__float2bfloat16(ra), __float2bfloat16(rb));
    return *(uint32_t*)&p;
}

__global__ void __launch_bounds__(256) k_gemm(const float* __restrict__ x,
                                              const float* __restrict__ expert_w,
                                              float* __restrict__ out) {
    extern __shared__ char smem[];
    uint32_t sb = smem_u32(smem);
    const uint32_t ws_base[2] = {sb, sb + WS_BYTES};
    const uint32_t xs_base[2] = {sb + 2*WS_BYTES, sb + 2*WS_BYTES + XS_BYTES};

    int tid  = threadIdx.x;
    int wid  = tid >> 5;
    int lane = tid & 31;
    int b    = blockIdx.y;
    int hw0  = blockIdx.x * 128;

    int   eidx  = g_idx[b];
    float scale = g_val[b];

    // ---- stage A: W[eidx] prescaled, hi/lo bf16.  thread: f=tid>>2, 16 c.
    {
        int f  = tid >> 2;
        int cq = tid & 3;                 // 16-c chunk
        const float4* Wp = (const float4*)(expert_w + ((size_t)eidx*C_ + f)*C_ + cq*16);
        uint32_t dst = f*WS_STRIDE + cq*32;
        uint32_t hi[8], lo[8];
#pragma unroll
        for (int q = 0; q < 4; q++) {
            float4 v = Wp[q];
            float a0 = scale*v.x, a1 = scale*v.y, a2 = scale*v.z, a3 = scale*v.w;
            hi[2*q]   = pack_hi(a0, a1);  hi[2*q+1] = pack_hi(a2, a3);
            lo[2*q]   = pack_lo(a0, a1);  lo[2*q+1] = pack_lo(a2, a3);
        }
#pragma unroll
        for (int h = 0; h < 2; h++) {
            asm volatile("st.shared.v4.b32 [%0], {%1,%2,%3,%4};" ::
                "r"(ws_base[0] + dst + h*16), "r"(hi[4*h]), "r"(hi[4*h+1]), "r"(hi[4*h+2]), "r"(hi[4*h+3]) : "memory");
            asm volatile("st.shared.v4.b32 [%0], {%1,%2,%3,%4};" ::
                "r"(ws_base[1] + dst + h*16), "r"(lo[4*h]), "r"(lo[4*h+1]), "r"(lo[4*h+2]), "r"(lo[4*h+3]) : "memory");
        }
    }

    // ---- stage B: x tile [64 c][128 hw] fp32 -> bf16 hi/lo.
    // thread: c = tid>>2, 32 hw at (tid&3)*32.
    {
        int c  = tid >> 2;
        int j0 = (tid & 3) * 32;
        const float4* Xp = (const float4*)(x + ((size_t)b*C_ + c)*HW_ + hw0 + j0);
        uint32_t dst = c*XS_STRIDE + j0*2;
#pragma unroll
        for (int h = 0; h < 4; h++) {     // 4 chunks of 8 floats
            float4 v0 = Xp[2*h], v1 = Xp[2*h+1];
            uint32_t h0 = pack_hi(v0.x, v0.y), h1 = pack_hi(v0.z, v0.w);
            uint32_t h2 = pack_hi(v1.x, v1.y), h3 = pack_hi(v1.z, v1.w);
            uint32_t l0 = pack_lo(v0.x, v0.y), l1 = pack_lo(v0.z, v0.w);
            uint32_t l2 = pack_lo(v1.x, v1.y), l3 = pack_lo(v1.z, v1.w);
            asm volatile("st.shared.v4.b32 [%0], {%1,%2,%3,%4};" ::
                "r"(xs_base[0] + dst + h*16), "r"(h0), "r"(h1), "r"(h2), "r"(h3) : "memory");
            asm volatile("st.shared.v4.b32 [%0], {%1,%2,%3,%4};" ::
                "r"(xs_base[1] + dst + h*16), "r"(l0), "r"(l1), "r"(l2), "r"(l3) : "memory");
        }
    }
    __syncthreads();

    // ---- compute: warp (wm, wn): f0 = wm*32, n0 = wn*32
    int wm = wid >> 2, wn = wid & 3;
    int f0 = wm * 32, n0 = wn * 32;

    float acc[2][4][4];
#pragma unroll
    for (int i = 0; i < 2; i++)
#pragma unroll
        for (int j = 0; j < 4; j++)
#pragma unroll
            for (int q = 0; q < 4; q++) acc[i][j][q] = 0.f;

    uint32_t a_lane = (uint32_t)((lane & 15) * WS_STRIDE + (lane >> 4) * 16);
    uint32_t b_lane = (uint32_t)((lane & 15) * XS_STRIDE + (lane >> 4) * 16);

    const int ta[3] = {0, 0, 1};   // term A source (hi, hi, lo)
    const int tb[3] = {0, 1, 0};   // term B source (hi, lo, hi)

#pragma unroll
    for (int t = 0; t < 3; t++) {
        uint32_t wa = ws_base[ta[t]];
        uint32_t xa = xs_base[tb[t]];
#pragma unroll
        for (int k = 0; k < 4; k++) {          // K = 64 in steps of 16
            uint32_t afr[2][4];
#pragma unroll
            for (int mi = 0; mi < 2; mi++)
                ldmat4(afr[mi], wa + (uint32_t)(f0 + mi*16)*WS_STRIDE + k*32 + a_lane);
            uint32_t bfr[2][4];
#pragma unroll
            for (int nj = 0; nj < 2; nj++)
                ldmat4t(bfr[nj], xa + (uint32_t)(k*16)*XS_STRIDE + (uint32_t)(n0 + nj*16)*2 + b_lane);
#pragma unroll
            for (int mi = 0; mi < 2; mi++) {
                mma16816(acc[mi][0], afr[mi], bfr[0][0], bfr[0][1]);
                mma16816(acc[mi][1], afr[mi], bfr[0][2], bfr[0][3]);
                mma16816(acc[mi][2], afr[mi], bfr[1][0], bfr[1][1]);
                mma16816(acc[mi][3], afr[mi], bfr[1][2], bfr[1][3]);
            }
        }
    }

    // ---- epilogue: direct coalesced float2 stores
    float* ob = out + (size_t)b * C_ * HW_ + hw0;
    int rrow = lane >> 2;
    int rcol = (lane & 3) * 2;
#pragma unroll
    for (int mi = 0; mi < 2; mi++) {
#pragma unroll
        for (int nj = 0; nj < 4; nj++) {
            float* p = ob + (size_t)(f0 + mi*16 + rrow) * HW_ + n0 + nj*8 + rcol;
            float2 v0; v0.x = acc[mi][nj][0]; v0.y = acc[mi][nj][1];
            float2 v1; v1.x = acc[mi][nj][2]; v1.y = acc[mi][nj][3];
            *(float2*)p = v0;
            *(float2*)(p + 8*HW_) = v1;
        }
    }
}

// ---------------------------------------------------------------------------
extern "C" void kernel_launch(void* const* d_in, const int* in_sizes, int n_in,
                              void* d_out, int out_size) {
    const float* x        = (const float*)d_in[0];
    const float* gate_w   = (const float*)d_in[1];
    const float* gate_b   = (const float*)d_in[2];
    const float* expert_w = (const float*)d_in[3];
    float* out = (float*)d_out;

    const int OUT_MAIN = B_*C_*HW_;
    float* ew = (out_size >= OUT_MAIN + B_*E_) ? (out + OUT_MAIN) : nullptr;

    cudaFuncSetAttribute(k_gemm, cudaFuncAttributeMaxDynamicSharedMemorySize, SMEM_TOT);

    k_winsum<<<B_*C_, 128>>>(x);
    k_gate<<<1, 256>>>(gate_w, gate_b, ew);
    k_gemm<<<dim3(HW_/128, B_), 256, SMEM_TOT>>>(x, expert_w, out);
}

// round 6
// speedup vs baseline: 3.9669x; 1.5187x over previous
#include <cuda_runtime.h>
#include <cuda_bf16.h>
#include <math.h>
#include <stdint.h>

#define B_ 32
#define C_ 64
#define H_ 64
#define W_ 64
#define E_ 8
#define HW_ (H_*W_)

// ---------------- scratch -------------------------------------------------
__device__ __align__(16) float g_S[B_*C_*9];

// ---------------------------------------------------------------------------
// Kernel 1: window sums via inclusion-exclusion. 2 images per 256-thr block.
// ---------------------------------------------------------------------------
__global__ void __launch_bounds__(256) k_winsum(const float* __restrict__ x) {
    int half = threadIdx.x >> 7;           // 0/1 image within block
    int tid  = threadIdx.x & 127;
    int bc   = blockIdx.x * 2 + half;

    const float4* img4 = (const float4*)(x + (size_t)bc * HW_);
    int xq = tid & 15;
    int ty = tid >> 4;

    float T = 0.f;
    float R0=0.f, R1=0.f, R2=0.f, R3=0.f;
    float C0=0.f, C1=0.f, C2=0.f, C3=0.f;

#pragma unroll
    for (int k = 0; k < 8; k++) {
        float4 v = img4[tid + k*128];
        float s = (v.x + v.y) + (v.z + v.w);
        T += s;
        int y = ty + k*8;
        if (y == 0)       R0 += s;
        else if (y == 1)  R1 += s;
        else if (y == 62) R2 += s;
        else if (y == 63) R3 += s;
        if (xq == 0)       { C0 += v.x; C1 += v.y; }
        else if (xq == 15) { C2 += v.z; C3 += v.w; }
    }

    float a[9] = {T, R0, R1, R2, R3, C0, C1, C2, C3};
#pragma unroll
    for (int off = 16; off; off >>= 1)
#pragma unroll
        for (int k = 0; k < 9; k++)
            a[k] += __shfl_down_sync(0xffffffffu, a[k], off);

    __shared__ float sred[8][9];
    int warp = threadIdx.x >> 5, lane = threadIdx.x & 31;
    if (lane == 0)
#pragma unroll
        for (int k = 0; k < 9; k++) sred[warp][k] = a[k];
    __syncthreads();

    if (tid == 0) {                         // one thread per image
        int w0 = half * 4;
        float r[9];
#pragma unroll
        for (int k = 0; k < 9; k++)
            r[k] = ((sred[w0][k] + sred[w0+1][k]) + (sred[w0+2][k] + sred[w0+3][k]));
        const float* img = x + (size_t)bc * HW_;
        const int yv[4] = {0, 1, 62, 63};
        float cv[4][4];
#pragma unroll
        for (int i = 0; i < 4; i++)
#pragma unroll
            for (int j = 0; j < 4; j++)
                cv[i][j] = img[yv[i]*64 + yv[j]];
        const int e0[3] = {2, 0, 0};
        const int e1[3] = {3, 3, 1};
        float* Sout = g_S + bc*9;
#pragma unroll
        for (int dy = 0; dy < 3; dy++) {
            int ya = e0[dy], yb = e1[dy];
#pragma unroll
            for (int dx = 0; dx < 3; dx++) {
                int xa = e0[dx], xb = e1[dx];
                Sout[dy*3+dx] = r[0]
                    - (r[1+ya] + r[1+yb]) - (r[5+xa] + r[5+xb])
                    + ((cv[ya][xa] + cv[ya][xb]) + (cv[yb][xa] + cv[yb][xb]));
            }
        }
    }
}

// ---------------------------------------------------------------------------
// Kernel 2: HMMA bf16 GEMM + fused gating.
// out[b,f,hw] = val[b] * sum_c W[idx[b]][f][c] * x[b,c,hw]
// 3-term split (truncation): Wh*xh + Wh*xl + Wl*xh, fp32 accum.
// CTA: 64 f x 128 hw; 8 warps of 32f x 32hw.
// ---------------------------------------------------------------------------
#define WS_STRIDE 144
#define XS_STRIDE 272
#define WS_BYTES  (64*WS_STRIDE)
#define XS_BYTES  (64*XS_STRIDE)
#define SMEM_TOT  (2*WS_BYTES + 2*XS_BYTES)   // 53248

__device__ __forceinline__ uint32_t smem_u32(const void* p) {
    uint32_t a;
    asm("{ .reg .u64 t; cvta.to.shared.u64 t, %1; cvt.u32.u64 %0, t; }" : "=r"(a) : "l"(p));
    return a;
}
__device__ __forceinline__ void ldmat4(uint32_t* r, uint32_t addr) {
    asm volatile("ldmatrix.sync.aligned.m8n8.x4.shared.b16 {%0,%1,%2,%3}, [%4];"
        : "=r"(r[0]), "=r"(r[1]), "=r"(r[2]), "=r"(r[3]) : "r"(addr));
}
__device__ __forceinline__ void ldmat4t(uint32_t* r, uint32_t addr) {
    asm volatile("ldmatrix.sync.aligned.m8n8.x4.trans.shared.b16 {%0,%1,%2,%3}, [%4];"
        : "=r"(r[0]), "=r"(r[1]), "=r"(r[2]), "=r"(r[3]) : "r"(addr));
}
__device__ __forceinline__ void mma16816(float* d, const uint32_t* a, uint32_t b0, uint32_t b1) {
    asm volatile("mma.sync.aligned.m16n8k16.row.col.f32.bf16.bf16.f32 "
        "{%0,%1,%2,%3}, {%4,%5,%6,%7}, {%8,%9}, {%0,%1,%2,%3};"
        : "+f"(d[0]), "+f"(d[1]), "+f"(d[2]), "+f"(d[3])
        : "r"(a[0]), "r"(a[1]), "r"(a[2]), "r"(a[3]), "r"(b0), "r"(b1));
}

// truncation split: hi = bits&0xFFFF0000 (exact bf16), lo = a - hi
__device__ __forceinline__ float trunc_hi(float a) {
    return __uint_as_float(__float_as_uint(a) & 0xFFFF0000u);
}
__device__ __forceinline__ uint32_t pack_hi2(float a, float b) {   // {lo16=bf(a), hi16=bf(b)}
    uint32_t r;
    asm("prmt.b32 %0, %1, %2, 0x7632;" : "=r"(r) : "r"(__float_as_uint(a)), "r"(__float_as_uint(b)));
    return r;
}
__device__ __forceinline__ uint32_t pack_lo2(float a, float b) {
    float la = a - trunc_hi(a);
    float lb = b - trunc_hi(b);
    uint32_t r;
    asm("cvt.rn.bf16x2.f32 %0, %1, %2;" : "=r"(r) : "f"(lb), "f"(la));
    return r;
}

__global__ void __launch_bounds__(256, 2) k_gemm(const float* __restrict__ x,
                                                 const float* __restrict__ expert_w,
                                                 const float* __restrict__ gate_w,
                                                 const float* __restrict__ gate_b,
                                                 float* __restrict__ out,
                                                 float* __restrict__ ew) {
    extern __shared__ char smem[];
    uint32_t sb = smem_u32(smem);
    const uint32_t ws_base[2] = {sb, sb + WS_BYTES};
    const uint32_t xs_base[2] = {sb + 2*WS_BYTES, sb + 2*WS_BYTES + XS_BYTES};
    __shared__ float sg[E_];

    int tid  = threadIdx.x;
    int wid  = tid >> 5;
    int lane = tid & 31;
    int b    = blockIdx.y;
    int hw0  = blockIdx.x * 128;

    // ---- fused gate: warp e computes gating code for expert e
    {
        const float* Wg = gate_w + wid * (C_*9);
        const float* Sb = g_S    + b   * (C_*9);
        float g = 0.f;
#pragma unroll
        for (int i = 0; i < 18; i++) {
            int j = lane + i*32;
            g += Wg[j] * Sb[j];
        }
#pragma unroll
        for (int off = 16; off; off >>= 1)
            g += __shfl_down_sync(0xffffffffu, g, off);
        if (lane == 0) sg[wid] = g + 3844.0f * gate_b[wid];
    }
    __syncthreads();

    float gv[E_];
#pragma unroll
    for (int e = 0; e < E_; e++) gv[e] = sg[e];
    float m = gv[0];
#pragma unroll
    for (int e = 1; e < E_; e++) m = fmaxf(m, gv[e]);
    float ssum = 0.f;
#pragma unroll
    for (int e = 0; e < E_; e++) ssum += expf(gv[e] - m);
    float scale = 1.0f / ssum;           // top-1 prob
    int eidx = 7;
#pragma unroll
    for (int e = 7; e >= 0; e--) if (gv[e] == m) eidx = e;   // lowest index wins

    if (ew && blockIdx.x == 0 && tid < E_)
        ew[b*E_ + tid] = (tid == eidx) ? scale : 0.f;

    // ---- stage A: W[eidx] prescaled, hi/lo bf16
    {
        int f  = tid >> 2;
        int cq = tid & 3;
        const float4* Wp = (const float4*)(expert_w + ((size_t)eidx*C_ + f)*C_ + cq*16);
        uint32_t dst = f*WS_STRIDE + cq*32;
        uint32_t hi[8], lo[8];
#pragma unroll
        for (int q = 0; q < 4; q++) {
            float4 v = Wp[q];
            float a0 = scale*v.x, a1 = scale*v.y, a2 = scale*v.z, a3 = scale*v.w;
            hi[2*q]   = pack_hi2(a0, a1);  hi[2*q+1] = pack_hi2(a2, a3);
            lo[2*q]   = pack_lo2(a0, a1);  lo[2*q+1] = pack_lo2(a2, a3);
        }
#pragma unroll
        for (int h = 0; h < 2; h++) {
            asm volatile("st.shared.v4.b32 [%0], {%1,%2,%3,%4};" ::
                "r"(ws_base[0] + dst + h*16), "r"(hi[4*h]), "r"(hi[4*h+1]), "r"(hi[4*h+2]), "r"(hi[4*h+3]) : "memory");
            asm volatile("st.shared.v4.b32 [%0], {%1,%2,%3,%4};" ::
                "r"(ws_base[1] + dst + h*16), "r"(lo[4*h]), "r"(lo[4*h+1]), "r"(lo[4*h+2]), "r"(lo[4*h+3]) : "memory");
        }
    }

    // ---- stage B: x tile [64 c][128 hw] -> bf16 hi/lo
    {
        int c  = tid >> 2;
        int j0 = (tid & 3) * 32;
        const float4* Xp = (const float4*)(x + ((size_t)b*C_ + c)*HW_ + hw0 + j0);
        uint32_t dst = c*XS_STRIDE + j0*2;
#pragma unroll
        for (int h = 0; h < 4; h++) {
            float4 v0 = Xp[2*h], v1 = Xp[2*h+1];
            uint32_t h0 = pack_hi2(v0.x, v0.y), h1 = pack_hi2(v0.z, v0.w);
            uint32_t h2 = pack_hi2(v1.x, v1.y), h3 = pack_hi2(v1.z, v1.w);
            uint32_t l0 = pack_lo2(v0.x, v0.y), l1 = pack_lo2(v0.z, v0.w);
            uint32_t l2 = pack_lo2(v1.x, v1.y), l3 = pack_lo2(v1.z, v1.w);
            asm volatile("st.shared.v4.b32 [%0], {%1,%2,%3,%4};" ::
                "r"(xs_base[0] + dst + h*16), "r"(h0), "r"(h1), "r"(h2), "r"(h3) : "memory");
            asm volatile("st.shared.v4.b32 [%0], {%1,%2,%3,%4};" ::
                "r"(xs_base[1] + dst + h*16), "r"(l0), "r"(l1), "r"(l2), "r"(l3) : "memory");
        }
    }
    __syncthreads();

    // ---- compute
    int wm = wid >> 2, wn = wid & 3;
    int f0 = wm * 32, n0 = wn * 32;

    float acc[2][4][4];
#pragma unroll
    for (int i = 0; i < 2; i++)
#pragma unroll
        for (int j = 0; j < 4; j++)
#pragma unroll
            for (int q = 0; q < 4; q++) acc[i][j][q] = 0.f;

    uint32_t a_lane = (uint32_t)((lane & 15) * WS_STRIDE + (lane >> 4) * 16);
    uint32_t b_lane = (uint32_t)((lane & 15) * XS_STRIDE + (lane >> 4) * 16);

    const int ta[3] = {0, 0, 1};
    const int tb[3] = {0, 1, 0};

#pragma unroll
    for (int t = 0; t < 3; t++) {
        uint32_t wa = ws_base[ta[t]];
        uint32_t xa = xs_base[tb[t]];
#pragma unroll
        for (int k = 0; k < 4; k++) {
            uint32_t afr[2][4];
#pragma unroll
            for (int mi = 0; mi < 2; mi++)
                ldmat4(afr[mi], wa + (uint32_t)(f0 + mi*16)*WS_STRIDE + k*32 + a_lane);
            uint32_t bfr[2][4];
#pragma unroll
            for (int nj = 0; nj < 2; nj++)
                ldmat4t(bfr[nj], xa + (uint32_t)(k*16)*XS_STRIDE + (uint32_t)(n0 + nj*16)*2 + b_lane);
#pragma unroll
            for (int mi = 0; mi < 2; mi++) {
                mma16816(acc[mi][0], afr[mi], bfr[0][0], bfr[0][1]);
                mma16816(acc[mi][1], afr[mi], bfr[0][2], bfr[0][3]);
                mma16816(acc[mi][2], afr[mi], bfr[1][0], bfr[1][1]);
                mma16816(acc[mi][3], afr[mi], bfr[1][2], bfr[1][3]);
            }
        }
    }

    // ---- epilogue
    float* ob = out + (size_t)b * C_ * HW_ + hw0;
    int rrow = lane >> 2;
    int rcol = (lane & 3) * 2;
#pragma unroll
    for (int mi = 0; mi < 2; mi++) {
#pragma unroll
        for (int nj = 0; nj < 4; nj++) {
            float* p = ob + (size_t)(f0 + mi*16 + rrow) * HW_ + n0 + nj*8 + rcol;
            float2 v0; v0.x = acc[mi][nj][0]; v0.y = acc[mi][nj][1];
            float2 v1; v1.x = acc[mi][nj][2]; v1.y = acc[mi][nj][3];
            *(float2*)p = v0;
            *(float2*)(p + 8*HW_) = v1;
        }
    }
}

// ---------------------------------------------------------------------------
extern "C" void kernel_launch(void* const* d_in, const int* in_sizes, int n_in,
                              void* d_out, int out_size) {
    const float* x        = (const float*)d_in[0];
    const float* gate_w   = (const float*)d_in[1];
    const float* gate_b   = (const float*)d_in[2];
    const float* expert_w = (const float*)d_in[3];
    float* out = (float*)d_out;

    const int OUT_MAIN = B_*C_*HW_;
    float* ew = (out_size >= OUT_MAIN + B_*E_) ? (out + OUT_MAIN) : nullptr;

    cudaFuncSetAttribute(k_gemm, cudaFuncAttributeMaxDynamicSharedMemorySize, SMEM_TOT);

    k_winsum<<<B_*C_/2, 256>>>(x);
    k_gemm<<<dim3(HW_/128, B_), 256, SMEM_TOT>>>(x, expert_w, gate_w, gate_b, out, ew);
}

// round 7
// speedup vs baseline: 4.1286x; 1.0408x over previous
#include <cuda_runtime.h>
#include <cuda_bf16.h>
#include <math.h>
#include <stdint.h>

#define B_ 32
#define C_ 64
#define H_ 64
#define W_ 64
#define E_ 8
#define HW_ (H_*W_)

// ---------------- scratch -------------------------------------------------
__device__ __align__(16) float g_S[B_*C_*9];
__device__ __align__(16) __nv_bfloat16 g_W[B_*128*64];   // per-b prescaled W: rows 0-63 hi, 64-127 lo

// ---------------------------------------------------------------------------
// helpers
// ---------------------------------------------------------------------------
__device__ __forceinline__ uint32_t smem_u32(const void* p) {
    uint32_t a;
    asm("{ .reg .u64 t; cvta.to.shared.u64 t, %1; cvt.u32.u64 %0, t; }" : "=r"(a) : "l"(p));
    return a;
}
__device__ __forceinline__ void ldmat4(uint32_t* r, uint32_t addr) {
    asm volatile("ldmatrix.sync.aligned.m8n8.x4.shared.b16 {%0,%1,%2,%3}, [%4];"
        : "=r"(r[0]), "=r"(r[1]), "=r"(r[2]), "=r"(r[3]) : "r"(addr));
}
__device__ __forceinline__ void ldmat4t(uint32_t* r, uint32_t addr) {
    asm volatile("ldmatrix.sync.aligned.m8n8.x4.trans.shared.b16 {%0,%1,%2,%3}, [%4];"
        : "=r"(r[0]), "=r"(r[1]), "=r"(r[2]), "=r"(r[3]) : "r"(addr));
}
__device__ __forceinline__ void mma16816(float* d, const uint32_t* a, uint32_t b0, uint32_t b1) {
    asm volatile("mma.sync.aligned.m16n8k16.row.col.f32.bf16.bf16.f32 "
        "{%0,%1,%2,%3}, {%4,%5,%6,%7}, {%8,%9}, {%0,%1,%2,%3};"
        : "+f"(d[0]), "+f"(d[1]), "+f"(d[2]), "+f"(d[3])
        : "r"(a[0]), "r"(a[1]), "r"(a[2]), "r"(a[3]), "r"(b0), "r"(b1));
}
__device__ __forceinline__ float trunc_hi(float a) {
    return __uint_as_float(__float_as_uint(a) & 0xFFFF0000u);
}
__device__ __forceinline__ uint32_t pack_hi2(float a, float b) {
    uint32_t r;
    asm("prmt.b32 %0, %1, %2, 0x7632;" : "=r"(r) : "r"(__float_as_uint(a)), "r"(__float_as_uint(b)));
    return r;
}
__device__ __forceinline__ uint32_t pack_lo2(float a, float b) {
    float la = a - trunc_hi(a);
    float lb = b - trunc_hi(b);
    uint32_t r;
    asm("cvt.rn.bf16x2.f32 %0, %1, %2;" : "=r"(r) : "f"(lb), "f"(la));
    return r;
}

// ---------------------------------------------------------------------------
// Kernel 1: window sums via inclusion-exclusion. 2 images per 256-thr block.
// ---------------------------------------------------------------------------
__global__ void __launch_bounds__(256) k_winsum(const float* __restrict__ x) {
    int half = threadIdx.x >> 7;
    int tid  = threadIdx.x & 127;
    int bc   = blockIdx.x * 2 + half;

    const float4* img4 = (const float4*)(x + (size_t)bc * HW_);
    int xq = tid & 15;
    int ty = tid >> 4;

    float T = 0.f;
    float R0=0.f, R1=0.f, R2=0.f, R3=0.f;
    float C0=0.f, C1=0.f, C2=0.f, C3=0.f;

#pragma unroll
    for (int k = 0; k < 8; k++) {
        float4 v = img4[tid + k*128];
        float s = (v.x + v.y) + (v.z + v.w);
        T += s;
        int y = ty + k*8;
        if (y == 0)       R0 += s;
        else if (y == 1)  R1 += s;
        else if (y == 62) R2 += s;
        else if (y == 63) R3 += s;
        if (xq == 0)       { C0 += v.x; C1 += v.y; }
        else if (xq == 15) { C2 += v.z; C3 += v.w; }
    }

    float a[9] = {T, R0, R1, R2, R3, C0, C1, C2, C3};
#pragma unroll
    for (int off = 16; off; off >>= 1)
#pragma unroll
        for (int k = 0; k < 9; k++)
            a[k] += __shfl_down_sync(0xffffffffu, a[k], off);

    __shared__ float sred[8][9];
    int warp = threadIdx.x >> 5, lane = threadIdx.x & 31;
    if (lane == 0)
#pragma unroll
        for (int k = 0; k < 9; k++) sred[warp][k] = a[k];
    __syncthreads();

    if (tid == 0) {
        int w0 = half * 4;
        float r[9];
#pragma unroll
        for (int k = 0; k < 9; k++)
            r[k] = ((sred[w0][k] + sred[w0+1][k]) + (sred[w0+2][k] + sred[w0+3][k]));
        const float* img = x + (size_t)bc * HW_;
        const int yv[4] = {0, 1, 62, 63};
        float cv[4][4];
#pragma unroll
        for (int i = 0; i < 4; i++)
#pragma unroll
            for (int j = 0; j < 4; j++)
                cv[i][j] = img[yv[i]*64 + yv[j]];
        const int e0[3] = {2, 0, 0};
        const int e1[3] = {3, 3, 1};
        float* Sout = g_S + bc*9;
#pragma unroll
        for (int dy = 0; dy < 3; dy++) {
            int ya = e0[dy], yb = e1[dy];
#pragma unroll
            for (int dx = 0; dx < 3; dx++) {
                int xa = e0[dx], xb = e1[dx];
                Sout[dy*3+dx] = r[0]
                    - (r[1+ya] + r[1+yb]) - (r[5+xa] + r[5+xb])
                    + ((cv[ya][xa] + cv[ya][xb]) + (cv[yb][xa] + cv[yb][xb]));
            }
        }
    }
}

// ---------------------------------------------------------------------------
// Kernel 2: per-b gate + softmax + top-1 + prescaled bf16 hi/lo W.
// grid = 32 (one block per b), 256 threads.
// ---------------------------------------------------------------------------
__global__ void __launch_bounds__(256) k_prep(const float* __restrict__ gate_w,
                                              const float* __restrict__ gate_b,
                                              const float* __restrict__ expert_w,
                                              float* __restrict__ ew) {
    __shared__ float sg[E_];
    int b    = blockIdx.x;
    int tid  = threadIdx.x;
    int wid  = tid >> 5;
    int lane = tid & 31;

    {
        const float* Wg = gate_w + wid * (C_*9);
        const float* Sb = g_S    + b   * (C_*9);
        float g = 0.f;
#pragma unroll
        for (int i = 0; i < 18; i++) {
            int j = lane + i*32;
            g += Wg[j] * Sb[j];
        }
#pragma unroll
        for (int off = 16; off; off >>= 1)
            g += __shfl_down_sync(0xffffffffu, g, off);
        if (lane == 0) sg[wid] = g + 3844.0f * gate_b[wid];
    }
    __syncthreads();

    float gv[E_];
#pragma unroll
    for (int e = 0; e < E_; e++) gv[e] = sg[e];
    float m = gv[0];
#pragma unroll
    for (int e = 1; e < E_; e++) m = fmaxf(m, gv[e]);
    float ssum = 0.f;
#pragma unroll
    for (int e = 0; e < E_; e++) ssum += expf(gv[e] - m);
    float scale = 1.0f / ssum;
    int eidx = 7;
#pragma unroll
    for (int e = 7; e >= 0; e--) if (gv[e] == m) eidx = e;

    if (ew && tid < E_)
        ew[b*E_ + tid] = (tid == eidx) ? scale : 0.f;

    // W[eidx] prescale + split: rows f hi, rows 64+f lo.  g_W[b] is [128][64].
    int f  = tid >> 2;
    int cq = tid & 3;
    const float4* Wp = (const float4*)(expert_w + ((size_t)eidx*C_ + f)*C_ + cq*16);
    uint32_t hi[8], lo[8];
#pragma unroll
    for (int q = 0; q < 4; q++) {
        float4 v = Wp[q];
        float a0 = scale*v.x, a1 = scale*v.y, a2 = scale*v.z, a3 = scale*v.w;
        hi[2*q]   = pack_hi2(a0, a1);  hi[2*q+1] = pack_hi2(a2, a3);
        lo[2*q]   = pack_lo2(a0, a1);  lo[2*q+1] = pack_lo2(a2, a3);
    }
    uint4* dh = (uint4*)(g_W + ((size_t)b*128 + f)      * 64 + cq*16);
    uint4* dl = (uint4*)(g_W + ((size_t)b*128 + 64 + f) * 64 + cq*16);
    dh[0] = make_uint4(hi[0], hi[1], hi[2], hi[3]);
    dh[1] = make_uint4(hi[4], hi[5], hi[6], hi[7]);
    dl[0] = make_uint4(lo[0], lo[1], lo[2], lo[3]);
    dl[1] = make_uint4(lo[4], lo[5], lo[6], lo[7]);
}

// ---------------------------------------------------------------------------
// Kernel 3: HMMA bf16 GEMM.  out[b,f,hw] = (Wh+Wl) @ (xh+xl) 3-term.
// CTA: 64 f x 128 hw; 8 warps of 32f x 32hw.  Shared-fragment mainloop:
// per k-step load Ah,Al,Bh,Bl once (8 ldmatrix quads) -> 24 MMAs.
// ---------------------------------------------------------------------------
#define WS_STRIDE 144
#define XS_STRIDE 272
#define WS_BYTES  (128*WS_STRIDE)          // 18432 (hi rows 0-63, lo rows 64-127)
#define XS_BYTES  (64*XS_STRIDE)           // 17408
#define SMEM_TOT  (WS_BYTES + 2*XS_BYTES)  // 53248

__global__ void __launch_bounds__(256, 2) k_gemm(const float* __restrict__ x,
                                                 float* __restrict__ out) {
    extern __shared__ char smem[];
    uint32_t sb = smem_u32(smem);
    const uint32_t ws = sb;
    const uint32_t xs_base[2] = {sb + WS_BYTES, sb + WS_BYTES + XS_BYTES};

    int tid  = threadIdx.x;
    int wid  = tid >> 5;
    int lane = tid & 31;
    int b    = blockIdx.y;
    int hw0  = blockIdx.x * 128;

    // ---- stage A: straight copy of prepared W (128 rows x 128B)
    {
        const uint4* Wp = (const uint4*)(g_W + (size_t)b * 128 * 64);
#pragma unroll
        for (int i = 0; i < 4; i++) {
            int id  = tid + i*256;        // 0..1023
            int row = id >> 3, c16 = id & 7;
            uint4 v = Wp[id];
            asm volatile("st.shared.v4.b32 [%0], {%1,%2,%3,%4};" ::
                "r"(ws + (uint32_t)(row*WS_STRIDE + c16*16)),
                "r"(v.x), "r"(v.y), "r"(v.z), "r"(v.w) : "memory");
        }
    }

    // ---- stage B: x tile [64 c][128 hw] -> bf16 hi/lo
    {
        int c  = tid >> 2;
        int j0 = (tid & 3) * 32;
        const float4* Xp = (const float4*)(x + ((size_t)b*C_ + c)*HW_ + hw0 + j0);
        uint32_t dst = c*XS_STRIDE + j0*2;
#pragma unroll
        for (int h = 0; h < 4; h++) {
            float4 v0 = Xp[2*h], v1 = Xp[2*h+1];
            uint32_t h0 = pack_hi2(v0.x, v0.y), h1 = pack_hi2(v0.z, v0.w);
            uint32_t h2 = pack_hi2(v1.x, v1.y), h3 = pack_hi2(v1.z, v1.w);
            uint32_t l0 = pack_lo2(v0.x, v0.y), l1 = pack_lo2(v0.z, v0.w);
            uint32_t l2 = pack_lo2(v1.x, v1.y), l3 = pack_lo2(v1.z, v1.w);
            asm volatile("st.shared.v4.b32 [%0], {%1,%2,%3,%4};" ::
                "r"(xs_base[0] + dst + h*16), "r"(h0), "r"(h1), "r"(h2), "r"(h3) : "memory");
            asm volatile("st.shared.v4.b32 [%0], {%1,%2,%3,%4};" ::
                "r"(xs_base[1] + dst + h*16), "r"(l0), "r"(l1), "r"(l2), "r"(l3) : "memory");
        }
    }
    __syncthreads();

    // ---- compute
    int wm = wid >> 2, wn = wid & 3;
    int f0 = wm * 32, n0 = wn * 32;

    float acc[2][4][4];
#pragma unroll
    for (int i = 0; i < 2; i++)
#pragma unroll
        for (int j = 0; j < 4; j++)
#pragma unroll
            for (int q = 0; q < 4; q++) acc[i][j][q] = 0.f;

    uint32_t a_lane = (uint32_t)((lane & 15) * WS_STRIDE + (lane >> 4) * 16);
    uint32_t b_lane = (uint32_t)((lane & 15) * XS_STRIDE + (lane >> 4) * 16);

#pragma unroll
    for (int k = 0; k < 4; k++) {
        uint32_t Ah[2][4], Al[2][4], Bh[2][4], Bl[2][4];
#pragma unroll
        for (int mi = 0; mi < 2; mi++) {
            ldmat4(Ah[mi], ws + (uint32_t)(f0 + mi*16)*WS_STRIDE      + k*32 + a_lane);
            ldmat4(Al[mi], ws + (uint32_t)(64 + f0 + mi*16)*WS_STRIDE + k*32 + a_lane);
        }
#pragma unroll
        for (int nj = 0; nj < 2; nj++) {
            ldmat4t(Bh[nj], xs_base[0] + (uint32_t)(k*16)*XS_STRIDE + (uint32_t)(n0 + nj*16)*2 + b_lane);
            ldmat4t(Bl[nj], xs_base[1] + (uint32_t)(k*16)*XS_STRIDE + (uint32_t)(n0 + nj*16)*2 + b_lane);
        }
#pragma unroll
        for (int mi = 0; mi < 2; mi++) {
#pragma unroll
            for (int nj = 0; nj < 2; nj++) {
                mma16816(acc[mi][nj*2],   Ah[mi], Bh[nj][0], Bh[nj][1]);
                mma16816(acc[mi][nj*2+1], Ah[mi], Bh[nj][2], Bh[nj][3]);
                mma16816(acc[mi][nj*2],   Ah[mi], Bl[nj][0], Bl[nj][1]);
                mma16816(acc[mi][nj*2+1], Ah[mi], Bl[nj][2], Bl[nj][3]);
                mma16816(acc[mi][nj*2],   Al[mi], Bh[nj][0], Bh[nj][1]);
                mma16816(acc[mi][nj*2+1], Al[mi], Bh[nj][2], Bh[nj][3]);
            }
        }
    }

    // ---- epilogue
    float* ob = out + (size_t)b * C_ * HW_ + hw0;
    int rrow = lane >> 2;
    int rcol = (lane & 3) * 2;
#pragma unroll
    for (int mi = 0; mi < 2; mi++) {
#pragma unroll
        for (int nj = 0; nj < 4; nj++) {
            float* p = ob + (size_t)(f0 + mi*16 + rrow) * HW_ + n0 + nj*8 + rcol;
            float2 v0; v0.x = acc[mi][nj][0]; v0.y = acc[mi][nj][1];
            float2 v1; v1.x = acc[mi][nj][2]; v1.y = acc[mi][nj][3];
            *(float2*)p = v0;
            *(float2*)(p + 8*HW_) = v1;
        }
    }
}

// ---------------------------------------------------------------------------
extern "C" void kernel_launch(void* const* d_in, const int* in_sizes, int n_in,
                              void* d_out, int out_size) {
    const float* x        = (const float*)d_in[0];
    const float* gate_w   = (const float*)d_in[1];
    const float* gate_b   = (const float*)d_in[2];
    const float* expert_w = (const float*)d_in[3];
    float* out = (float*)d_out;

    const int OUT_MAIN = B_*C_*HW_;
    float* ew = (out_size >= OUT_MAIN + B_*E_) ? (out + OUT_MAIN) : nullptr;

    cudaFuncSetAttribute(k_gemm, cudaFuncAttributeMaxDynamicSharedMemorySize, SMEM_TOT);

    k_winsum<<<B_*C_/2, 256>>>(x);
    k_prep<<<B_, 256>>>(gate_w, gate_b, expert_w, ew);
    k_gemm<<<dim3(HW_/128, B_), 256, SMEM_TOT>>>(x, out);
}